// round 1
// baseline (speedup 1.0000x reference)
#include <cuda_runtime.h>
#include <math.h>

#define N   16384
#define D   768
#define DH  384
#define BM  64
#define BK  16
#define NB  (N / BM)

// Scratch (allocation-free rule: __device__ globals)
__device__ float              g_x[(size_t)N * D];      // normalized vectors, 48 MB (L2-resident)
__device__ unsigned long long g_best[N];               // packed (sortable dot << 32) | (~j)
__device__ float              g_logd[N];               // per-row log distance

// Map float to monotonically sortable uint32
__device__ __forceinline__ unsigned f2s(float f) {
    unsigned u = __float_as_uint(f);
    return u ^ ((u & 0x80000000u) ? 0xFFFFFFFFu : 0x80000000u);
}

// ---------------------------------------------------------------------------
// Kernel 1: concat + L2 normalize, one block per row. Also inits g_best.
// ---------------------------------------------------------------------------
__global__ void normalize_kernel(const float* __restrict__ a,
                                 const float* __restrict__ b) {
    int r = blockIdx.x;
    int t = threadIdx.x;  // 256 threads, 3 elements each (768 = 3*256)
    float v[3];
    float ss = 0.f;
#pragma unroll
    for (int p = 0; p < 3; p++) {
        int k = t + p * 256;
        float x = (k < DH) ? a[(size_t)r * DH + k] : b[(size_t)r * DH + (k - DH)];
        v[p] = x;
        ss += x * x;
    }
    __shared__ float red[256];
    red[t] = ss;
    __syncthreads();
#pragma unroll
    for (int s = 128; s > 0; s >>= 1) {
        if (t < s) red[t] += red[t + s];
        __syncthreads();
    }
    float inv = 1.0f / fmaxf(sqrtf(red[0]), 1e-8f);
#pragma unroll
    for (int p = 0; p < 3; p++)
        g_x[(size_t)r * D + t + p * 256] = v[p] * inv;
    if (t == 0) g_best[r] = 0ull;  // below f2s(-1) = 0x407FFFFF, safe floor
}

// ---------------------------------------------------------------------------
// Kernel 2: symmetric tiled GEMM (64x64x16, fp32, 4x4 per thread) with fused
// per-row AND per-col argmax epilogue (symmetry: dot[i,j]==dot[j,i]).
// Only upper-triangle tiles (bj >= bi) do work.
// ---------------------------------------------------------------------------
__global__ void __launch_bounds__(256) gemm_argmax_kernel() {
    int bi = blockIdx.y, bj = blockIdx.x;
    if (bj < bi) return;

    __shared__ float As[BK][BM + 4];
    __shared__ float Bs[BK][BM + 4];
    __shared__ float sC[BM][BM + 1];

    int tid = threadIdx.x;
    int tx = tid & 15;      // n-dim 0..15
    int ty = tid >> 4;      // m-dim 0..15
    int row0 = bi * BM, col0 = bj * BM;

    float acc[4][4] = {};

    int lm = tid >> 2;              // 0..63 : tile row
    int lk = (tid & 3) << 2;        // 0,4,8,12 : k offset (float4)
    const float* Ab = g_x + (size_t)(row0 + lm) * D + lk;
    const float* Bb = g_x + (size_t)(col0 + lm) * D + lk;

    for (int k0 = 0; k0 < D; k0 += BK) {
        float4 av = *(const float4*)(Ab + k0);
        float4 bv = *(const float4*)(Bb + k0);
        __syncthreads();
        As[lk + 0][lm] = av.x; As[lk + 1][lm] = av.y;
        As[lk + 2][lm] = av.z; As[lk + 3][lm] = av.w;
        Bs[lk + 0][lm] = bv.x; Bs[lk + 1][lm] = bv.y;
        Bs[lk + 2][lm] = bv.z; Bs[lk + 3][lm] = bv.w;
        __syncthreads();
#pragma unroll
        for (int k = 0; k < BK; k++) {
            float4 a4 = *(const float4*)&As[k][ty * 4];
            float4 b4 = *(const float4*)&Bs[k][tx * 4];
            float ar[4] = {a4.x, a4.y, a4.z, a4.w};
            float br[4] = {b4.x, b4.y, b4.z, b4.w};
#pragma unroll
            for (int i = 0; i < 4; i++)
#pragma unroll
                for (int j = 0; j < 4; j++)
                    acc[i][j] += ar[i] * br[j];
        }
    }

    // Stage the 64x64 tile in smem for the two argmax scans
#pragma unroll
    for (int i = 0; i < 4; i++)
#pragma unroll
        for (int j = 0; j < 4; j++)
            sC[ty * 4 + i][tx * 4 + j] = acc[i][j];
    __syncthreads();

    if (tid < 64) {
        // row scan: row (row0+tid) vs cols [col0, col0+64)
        int gi = row0 + tid;
        float best = -2.f;
        int   bidx = 0;
        for (int j = 0; j < BM; j++) {
            int gj = col0 + j;
            float vv = sC[tid][j];
            if (gj != gi && vv > best) { best = vv; bidx = gj; }
        }
        unsigned long long pk =
            ((unsigned long long)f2s(best) << 32) |
            (unsigned long long)(0xFFFFFFFFu - (unsigned)bidx);
        atomicMax(&g_best[gi], pk);
    } else if (tid < 128) {
        // col scan: treats col (col0+c) as a row via symmetry, vs [row0, row0+64)
        int c = tid - 64;
        int gj = col0 + c;
        float best = -2.f;
        int   bidx = 0;
        for (int i = 0; i < BM; i++) {
            int gi = row0 + i;
            float vv = sC[i][c];
            if (gi != gj && vv > best) { best = vv; bidx = gi; }
        }
        unsigned long long pk =
            ((unsigned long long)f2s(best) << 32) |
            (unsigned long long)(0xFFFFFFFFu - (unsigned)bidx);
        atomicMax(&g_best[gj], pk);
    }
}

// ---------------------------------------------------------------------------
// Kernel 3: per-row distance to nearest neighbor, log
// ---------------------------------------------------------------------------
__global__ void dist_kernel() {
    int r = blockIdx.x;
    int t = threadIdx.x;  // 128
    unsigned long long pk = g_best[r];
    int j = (int)(0xFFFFFFFFu - (unsigned)(pk & 0xFFFFFFFFu));
    const float* xr = g_x + (size_t)r * D;
    const float* xj = g_x + (size_t)j * D;
    float ss = 0.f;
    for (int k = t; k < D; k += 128) {
        float d = xr[k] - xj[k] + 1e-8f;
        ss += d * d;
    }
    __shared__ float red[128];
    red[t] = ss;
    __syncthreads();
#pragma unroll
    for (int s = 64; s > 0; s >>= 1) {
        if (t < s) red[t] += red[t + s];
        __syncthreads();
    }
    if (t == 0) g_logd[r] = logf(sqrtf(red[0]) + 1e-8f);
}

// ---------------------------------------------------------------------------
// Kernel 4: deterministic final mean reduce
// ---------------------------------------------------------------------------
__global__ void reduce_kernel(float* __restrict__ out) {
    __shared__ float red[512];
    int t = threadIdx.x;
    float s = 0.f;
    for (int i = t; i < N; i += 512) s += g_logd[i];
    red[t] = s;
    __syncthreads();
#pragma unroll
    for (int k = 256; k > 0; k >>= 1) {
        if (t < k) red[t] += red[t + k];
        __syncthreads();
    }
    if (t == 0) out[0] = -red[0] / (float)N;
}

extern "C" void kernel_launch(void* const* d_in, const int* in_sizes, int n_in,
                              void* d_out, int out_size) {
    const float* a = (const float*)d_in[0];
    const float* b = (const float*)d_in[1];
    float* out = (float*)d_out;

    normalize_kernel<<<N, 256>>>(a, b);

    dim3 grid(NB, NB);
    gemm_argmax_kernel<<<grid, 256>>>();

    dist_kernel<<<N, 128>>>();
    reduce_kernel<<<1, 512>>>(out);
}

// round 3
// speedup vs baseline: 5.0344x; 5.0344x over previous
#include <cuda_runtime.h>
#include <cuda_bf16.h>
#include <math.h>
#include <stdint.h>

#define N   16384
#define D   768
#define DH  384
#define BM  128
#define NB  (N / BM)        // 128
#define BK  32
#define NSTEP (D / BK)      // 24

// smem tile layout: padded rows of 40 bf16 (80 B) -> conflict-free ldmatrix
#define LDT 40
#define TILE_BYTES (128 * LDT * 2)          // 10240
#define BUF_BYTES  (2 * TILE_BYTES)         // A+B = 20480
#define SMEM_TOTAL 66560                    // max(2*BUF_BYTES=40960, sC 128*130*4=66560)

// ---- device globals (allocation-free scratch) ----
__device__ float              g_x [(size_t)N * D];   // fp32 normalized (48 MB)
__device__ __nv_bfloat16      g_xb[(size_t)N * D];   // bf16 row-major (24 MB)
__device__ unsigned long long g_best[N];
__device__ float              g_logd[N];

__device__ __forceinline__ uint32_t smem_u32(const void* p) {
    uint32_t a;
    asm("{ .reg .u64 t; cvta.to.shared.u64 t, %1; cvt.u32.u64 %0, t; }" : "=r"(a) : "l"(p));
    return a;
}
__device__ __forceinline__ unsigned f2s(float f) {
    unsigned u = __float_as_uint(f);
    return u ^ ((u & 0x80000000u) ? 0xFFFFFFFFu : 0x80000000u);
}
__device__ __forceinline__ void cp16(uint32_t s, const void* g) {
    asm volatile("cp.async.ca.shared.global [%0], [%1], 16;" :: "r"(s), "l"(g) : "memory");
}
__device__ __forceinline__ void cp_commit() {
    asm volatile("cp.async.commit_group;" ::: "memory");
}
template <int K>
__device__ __forceinline__ void cp_wait() {
    asm volatile("cp.async.wait_group %0;" :: "n"(K) : "memory");
}
__device__ __forceinline__ void ldm_x4(uint32_t& r0, uint32_t& r1, uint32_t& r2, uint32_t& r3,
                                       uint32_t addr) {
    asm volatile("ldmatrix.sync.aligned.m8n8.x4.shared.b16 {%0,%1,%2,%3}, [%4];"
                 : "=r"(r0), "=r"(r1), "=r"(r2), "=r"(r3) : "r"(addr));
}
__device__ __forceinline__ void mma_bf16(float* d, const uint32_t* a, const uint32_t* b) {
    asm volatile(
        "mma.sync.aligned.m16n8k16.row.col.f32.bf16.bf16.f32 "
        "{%0,%1,%2,%3}, {%4,%5,%6,%7}, {%8,%9}, {%0,%1,%2,%3};"
        : "+f"(d[0]), "+f"(d[1]), "+f"(d[2]), "+f"(d[3])
        : "r"(a[0]), "r"(a[1]), "r"(a[2]), "r"(a[3]), "r"(b[0]), "r"(b[1]));
}

// ---------------------------------------------------------------------------
// Kernel 1: concat + L2 normalize -> fp32 g_x and bf16 g_xb. Inits g_best.
// ---------------------------------------------------------------------------
__global__ void __launch_bounds__(256) normalize_kernel(const float* __restrict__ a,
                                                        const float* __restrict__ b) {
    int r = blockIdx.x;
    int t = threadIdx.x;
    float v[3];
    float ss = 0.f;
#pragma unroll
    for (int p = 0; p < 3; p++) {
        int k = t + p * 256;
        float x = (k < DH) ? a[(size_t)r * DH + k] : b[(size_t)r * DH + (k - DH)];
        v[p] = x;
        ss += x * x;
    }
    __shared__ float red[256];
    red[t] = ss;
    __syncthreads();
#pragma unroll
    for (int s = 128; s > 0; s >>= 1) {
        if (t < s) red[t] += red[t + s];
        __syncthreads();
    }
    float inv = 1.0f / fmaxf(sqrtf(red[0]), 1e-8f);
#pragma unroll
    for (int p = 0; p < 3; p++) {
        int k = t + p * 256;
        float y = v[p] * inv;
        g_x[(size_t)r * D + k]  = y;
        g_xb[(size_t)r * D + k] = __float2bfloat16(y);
    }
    if (t == 0) g_best[r] = 0ull;
}

// ---------------------------------------------------------------------------
// Kernel 2: bf16 HMMA 128x128x768 tile GEMM + fused symmetric dual argmax.
// Upper-triangle tiles only (bj >= bi).
// ---------------------------------------------------------------------------
__global__ void __launch_bounds__(256, 1) gemm_argmax_hmma() {
    extern __shared__ char smem[];
    int bi = blockIdx.y, bj = blockIdx.x;
    if (bj < bi) return;

    uint32_t sb = smem_u32(smem);
    int tid  = threadIdx.x;
    int lane = tid & 31;
    int wid  = tid >> 5;
    int wm = wid >> 1;          // 0..3 -> 32-row strip
    int wn = wid & 1;           // 0..1 -> 64-col strip
    int row0 = bi * BM, col0 = bj * BM;

    // fill buffer `buf` with k-step `s` (A tile rows=row0.., B tile rows=col0..)
    auto fill = [&](int s, int buf) {
        uint32_t base = sb + buf * BUF_BYTES;
        int k0 = s * BK;
#pragma unroll
        for (int h = 0; h < 2; h++) {
            int id  = tid * 2 + h;       // 0..511
            int row = id >> 2;
            int seg = id & 3;
            // A
            cp16(base + row * 80 + seg * 16,
                 g_xb + (size_t)(row0 + row) * D + k0 + seg * 8);
            // B
            cp16(base + TILE_BYTES + row * 80 + seg * 16,
                 g_xb + (size_t)(col0 + row) * D + k0 + seg * 8);
        }
    };

    float acc[2][8][4];
#pragma unroll
    for (int i = 0; i < 2; i++)
#pragma unroll
        for (int j = 0; j < 8; j++)
#pragma unroll
            for (int q = 0; q < 4; q++) acc[i][j][q] = 0.f;

    fill(0, 0);
    cp_commit();

    for (int s = 0; s < NSTEP; s++) {
        int buf = s & 1;
        if (s + 1 < NSTEP) {
            fill(s + 1, buf ^ 1);
            cp_commit();
            cp_wait<1>();
        } else {
            cp_wait<0>();
        }
        __syncthreads();

        uint32_t Ab = sb + buf * BUF_BYTES;
        uint32_t Bb = Ab + TILE_BYTES;
#pragma unroll
        for (int kh = 0; kh < 2; kh++) {
            int k0 = kh * 16;
            uint32_t af[2][4];
#pragma unroll
            for (int i = 0; i < 2; i++) {
                uint32_t addr = Ab + (wm * 32 + i * 16 + (lane & 15)) * 80 +
                                (k0 + (lane >> 4) * 8) * 2;
                ldm_x4(af[i][0], af[i][1], af[i][2], af[i][3], addr);
            }
            uint32_t bf[8][2];
#pragma unroll
            for (int jp = 0; jp < 4; jp++) {
                int n0 = wn * 64 + jp * 16;
                uint32_t addr = Bb + (n0 + (lane & 7) + (lane >> 4) * 8) * 80 +
                                (k0 + ((lane >> 3) & 1) * 8) * 2;
                uint32_t b0, b1, b2, b3;
                ldm_x4(b0, b1, b2, b3, addr);
                bf[jp * 2][0] = b0;     bf[jp * 2][1] = b1;
                bf[jp * 2 + 1][0] = b2; bf[jp * 2 + 1][1] = b3;
            }
#pragma unroll
            for (int i = 0; i < 2; i++)
#pragma unroll
                for (int j = 0; j < 8; j++)
                    mma_bf16(acc[i][j], af[i], bf[j]);
        }
        __syncthreads();
    }

    // ---- epilogue: stage 128x128 fp32 tile, dual argmax ----
    float* sC = (float*)smem;  // [128][130]
#pragma unroll
    for (int i = 0; i < 2; i++)
#pragma unroll
        for (int j = 0; j < 8; j++) {
            int r = wm * 32 + i * 16 + (lane >> 2);
            int c = wn * 64 + j * 8 + (lane & 3) * 2;
            sC[r * 130 + c]           = acc[i][j][0];
            sC[r * 130 + c + 1]       = acc[i][j][1];
            sC[(r + 8) * 130 + c]     = acc[i][j][2];
            sC[(r + 8) * 130 + c + 1] = acc[i][j][3];
        }
    __syncthreads();

    if (tid < 128) {
        int gi = row0 + tid;
        float best = -2.f;
        int bidx = 0;
        for (int j = 0; j < BM; j++) {
            float v = sC[tid * 130 + j];
            int gj = col0 + j;
            if (gj != gi && v > best) { best = v; bidx = gj; }
        }
        unsigned long long pk =
            ((unsigned long long)f2s(best) << 32) |
            (unsigned long long)(0xFFFFFFFFu - (unsigned)bidx);
        atomicMax(&g_best[gi], pk);
    } else {
        int c = tid - 128;
        int gj = col0 + c;
        float best = -2.f;
        int bidx = 0;
        for (int i = 0; i < BM; i++) {
            float v = sC[i * 130 + c];
            int gi = row0 + i;
            if (gi != gj && v > best) { best = v; bidx = gi; }
        }
        unsigned long long pk =
            ((unsigned long long)f2s(best) << 32) |
            (unsigned long long)(0xFFFFFFFFu - (unsigned)bidx);
        atomicMax(&g_best[gj], pk);
    }
}

// ---------------------------------------------------------------------------
// Kernel 3: per-row NN distance (fp32 vectors), log
// ---------------------------------------------------------------------------
__global__ void dist_kernel() {
    int r = blockIdx.x;
    int t = threadIdx.x;
    unsigned long long pk = g_best[r];
    int j = (int)(0xFFFFFFFFu - (unsigned)(pk & 0xFFFFFFFFu));
    const float* xr = g_x + (size_t)r * D;
    const float* xj = g_x + (size_t)j * D;
    float ss = 0.f;
    for (int k = t; k < D; k += 128) {
        float d = xr[k] - xj[k] + 1e-8f;
        ss += d * d;
    }
    __shared__ float red[128];
    red[t] = ss;
    __syncthreads();
#pragma unroll
    for (int s = 64; s > 0; s >>= 1) {
        if (t < s) red[t] += red[t + s];
        __syncthreads();
    }
    if (t == 0) g_logd[r] = logf(sqrtf(red[0]) + 1e-8f);
}

// ---------------------------------------------------------------------------
// Kernel 4: final mean
// ---------------------------------------------------------------------------
__global__ void reduce_kernel(float* __restrict__ out) {
    __shared__ float red[512];
    int t = threadIdx.x;
    float s = 0.f;
    for (int i = t; i < N; i += 512) s += g_logd[i];
    red[t] = s;
    __syncthreads();
#pragma unroll
    for (int k = 256; k > 0; k >>= 1) {
        if (t < k) red[t] += red[t + k];
        __syncthreads();
    }
    if (t == 0) out[0] = -red[0] / (float)N;
}

extern "C" void kernel_launch(void* const* d_in, const int* in_sizes, int n_in,
                              void* d_out, int out_size) {
    const float* a = (const float*)d_in[0];
    const float* b = (const float*)d_in[1];
    float* out = (float*)d_out;

    static int configured = 0;
    cudaFuncSetAttribute(gemm_argmax_hmma,
                         cudaFuncAttributeMaxDynamicSharedMemorySize, SMEM_TOTAL);
    (void)configured;

    normalize_kernel<<<N, 256>>>(a, b);

    dim3 grid(NB, NB);
    gemm_argmax_hmma<<<grid, 256, SMEM_TOTAL>>>();

    dist_kernel<<<N, 128>>>();
    reduce_kernel<<<1, 512>>>(out);
}

// round 4
// speedup vs baseline: 6.7044x; 1.3317x over previous
#include <cuda_runtime.h>
#include <cuda_bf16.h>
#include <math.h>
#include <stdint.h>

#define N   16384
#define D   768
#define DH  384
#define BM  128
#define NB  (N / BM)        // 128
#define BK  32
#define NSTEP (D / BK)      // 24

// smem tile: padded rows of 40 bf16 (80 B) -> conflict-free ldmatrix
#define LDT 40
#define TILE_BYTES (128 * LDT * 2)          // 10240
#define BUF_BYTES  (2 * TILE_BYTES)         // A+B = 20480
#define NSTAGE 3
#define SMEM_TOTAL (NSTAGE * BUF_BYTES)     // 61440

// ---- device globals (allocation-free scratch) ----
__device__ float              g_x [(size_t)N * D];   // fp32 normalized (48 MB)
__device__ __nv_bfloat16      g_xb[(size_t)N * D];   // bf16 row-major (24 MB)
__device__ unsigned long long g_best[N];
__device__ float              g_logd[N];

__device__ __forceinline__ uint32_t smem_u32(const void* p) {
    uint32_t a;
    asm("{ .reg .u64 t; cvta.to.shared.u64 t, %1; cvt.u32.u64 %0, t; }" : "=r"(a) : "l"(p));
    return a;
}
__device__ __forceinline__ unsigned f2s(float f) {
    unsigned u = __float_as_uint(f);
    return u ^ ((u & 0x80000000u) ? 0xFFFFFFFFu : 0x80000000u);
}
__device__ __forceinline__ void cp16(uint32_t s, const void* g) {
    asm volatile("cp.async.ca.shared.global [%0], [%1], 16;" :: "r"(s), "l"(g) : "memory");
}
__device__ __forceinline__ void cp_commit() {
    asm volatile("cp.async.commit_group;" ::: "memory");
}
template <int K>
__device__ __forceinline__ void cp_wait() {
    asm volatile("cp.async.wait_group %0;" :: "n"(K) : "memory");
}
__device__ __forceinline__ void ldm_x4(uint32_t& r0, uint32_t& r1, uint32_t& r2, uint32_t& r3,
                                       uint32_t addr) {
    asm volatile("ldmatrix.sync.aligned.m8n8.x4.shared.b16 {%0,%1,%2,%3}, [%4];"
                 : "=r"(r0), "=r"(r1), "=r"(r2), "=r"(r3) : "r"(addr));
}
__device__ __forceinline__ void mma_bf16(float* d, const uint32_t* a, const uint32_t* b) {
    asm volatile(
        "mma.sync.aligned.m16n8k16.row.col.f32.bf16.bf16.f32 "
        "{%0,%1,%2,%3}, {%4,%5,%6,%7}, {%8,%9}, {%0,%1,%2,%3};"
        : "+f"(d[0]), "+f"(d[1]), "+f"(d[2]), "+f"(d[3])
        : "r"(a[0]), "r"(a[1]), "r"(a[2]), "r"(a[3]), "r"(b[0]), "r"(b[1]));
}
__device__ __forceinline__ unsigned long long pmax(unsigned long long a, unsigned long long b) {
    return a > b ? a : b;
}

// ---------------------------------------------------------------------------
// Kernel 1: concat + L2 normalize -> fp32 g_x and bf16 g_xb. Inits g_best.
// ---------------------------------------------------------------------------
__global__ void __launch_bounds__(256) normalize_kernel(const float* __restrict__ a,
                                                        const float* __restrict__ b) {
    int r = blockIdx.x;
    int t = threadIdx.x;
    float v[3];
    float ss = 0.f;
#pragma unroll
    for (int p = 0; p < 3; p++) {
        int k = t + p * 256;
        float x = (k < DH) ? a[(size_t)r * DH + k] : b[(size_t)r * DH + (k - DH)];
        v[p] = x;
        ss += x * x;
    }
    __shared__ float red[256];
    red[t] = ss;
    __syncthreads();
#pragma unroll
    for (int s = 128; s > 0; s >>= 1) {
        if (t < s) red[t] += red[t + s];
        __syncthreads();
    }
    float inv = 1.0f / fmaxf(sqrtf(red[0]), 1e-8f);
#pragma unroll
    for (int p = 0; p < 3; p++) {
        int k = t + p * 256;
        float y = v[p] * inv;
        g_x[(size_t)r * D + k]  = y;
        g_xb[(size_t)r * D + k] = __float2bfloat16(y);
    }
    if (t == 0) g_best[r] = 0ull;
}

// ---------------------------------------------------------------------------
// Kernel 2: bf16 HMMA 128x128x768 tile GEMM + fused symmetric dual argmax.
// 3-stage cp.async pipeline, register-shuffle epilogue, 2 CTAs/SM.
// Upper-triangle tiles only (bj >= bi).
// ---------------------------------------------------------------------------
__global__ void __launch_bounds__(256, 2) gemm_argmax_hmma() {
    extern __shared__ char smem[];
    int bi = blockIdx.y, bj = blockIdx.x;
    if (bj < bi) return;

    uint32_t sb = smem_u32(smem);
    int tid  = threadIdx.x;
    int lane = tid & 31;
    int wid  = tid >> 5;
    int wm = wid >> 1;          // 0..3 -> 32-row strip
    int wn = wid & 1;           // 0..1 -> 64-col strip
    int row0 = bi * BM, col0 = bj * BM;

    // precomputed fill addresses: each thread moves 2x16B for A and B
    int id0 = tid * 2, id1 = tid * 2 + 1;
    int r_0 = id0 >> 2, s_0 = id0 & 3;
    int r_1 = id1 >> 2, s_1 = id1 & 3;
    const char* gA0 = (const char*)(g_xb + (size_t)(row0 + r_0) * D + s_0 * 8);
    const char* gA1 = (const char*)(g_xb + (size_t)(row0 + r_1) * D + s_1 * 8);
    const char* gB0 = (const char*)(g_xb + (size_t)(col0 + r_0) * D + s_0 * 8);
    const char* gB1 = (const char*)(g_xb + (size_t)(col0 + r_1) * D + s_1 * 8);
    uint32_t sA0 = r_0 * 80 + s_0 * 16, sA1 = r_1 * 80 + s_1 * 16;

    auto fill = [&](int s, int buf) {
        uint32_t base = sb + buf * BUF_BYTES;
        size_t kb = (size_t)(s * BK) * 2;   // byte offset along k
        cp16(base + sA0, gA0 + kb);
        cp16(base + sA1, gA1 + kb);
        cp16(base + TILE_BYTES + sA0, gB0 + kb);
        cp16(base + TILE_BYTES + sA1, gB1 + kb);
    };

    float acc[2][8][4];
#pragma unroll
    for (int i = 0; i < 2; i++)
#pragma unroll
        for (int j = 0; j < 8; j++)
#pragma unroll
            for (int q = 0; q < 4; q++) acc[i][j][q] = 0.f;

    fill(0, 0); cp_commit();
    fill(1, 1); cp_commit();

    for (int s = 0; s < NSTEP; s++) {
        int buf = s % NSTAGE;
        if (s + 2 < NSTEP) cp_wait<1>(); else cp_wait<0>();
        __syncthreads();
        if (s + 2 < NSTEP) { fill(s + 2, (s + 2) % NSTAGE); cp_commit(); }

        uint32_t Ab = sb + buf * BUF_BYTES;
        uint32_t Bb = Ab + TILE_BYTES;
#pragma unroll
        for (int kh = 0; kh < 2; kh++) {
            int k0 = kh * 16;
            uint32_t af[2][4];
#pragma unroll
            for (int i = 0; i < 2; i++) {
                uint32_t addr = Ab + (wm * 32 + i * 16 + (lane & 15)) * 80 +
                                (k0 + (lane >> 4) * 8) * 2;
                ldm_x4(af[i][0], af[i][1], af[i][2], af[i][3], addr);
            }
            uint32_t bfr[8][2];
#pragma unroll
            for (int jp = 0; jp < 4; jp++) {
                int n0 = wn * 64 + jp * 16;
                uint32_t addr = Bb + (n0 + (lane & 7) + (lane >> 4) * 8) * 80 +
                                (k0 + ((lane >> 3) & 1) * 8) * 2;
                uint32_t b0, b1, b2, b3;
                ldm_x4(b0, b1, b2, b3, addr);
                bfr[jp * 2][0] = b0;     bfr[jp * 2][1] = b1;
                bfr[jp * 2 + 1][0] = b2; bfr[jp * 2 + 1][1] = b3;
            }
#pragma unroll
            for (int i = 0; i < 2; i++)
#pragma unroll
                for (int j = 0; j < 8; j++)
                    mma_bf16(acc[i][j], af[i], bfr[j]);
        }
        __syncthreads();
    }

    // ---- epilogue: register-space dual argmax via packed-u64 shuffles ----
    // fragment map: acc[i][j][h*2+q] -> row = wm*32+i*16+h*8+(lane>>2),
    //                                   col = wn*64+j*8+(lane&3)*2+q

    // row argmax (reduce over lane&3 : the 4 lanes sharing a row)
#pragma unroll
    for (int i = 0; i < 2; i++) {
#pragma unroll
        for (int h = 0; h < 2; h++) {
            int gi = row0 + wm * 32 + i * 16 + h * 8 + (lane >> 2);
            float bv = -2.f;
            int bc = 0;
#pragma unroll
            for (int j = 0; j < 8; j++) {
#pragma unroll
                for (int q = 0; q < 2; q++) {
                    int gj = col0 + wn * 64 + j * 8 + (lane & 3) * 2 + q;
                    float v = acc[i][j][h * 2 + q];
                    if (gj != gi && v > bv) { bv = v; bc = gj; }
                }
            }
            unsigned long long pk =
                ((unsigned long long)f2s(bv) << 32) |
                (unsigned long long)(0xFFFFFFFFu - (unsigned)bc);
            pk = pmax(pk, __shfl_xor_sync(0xffffffffu, pk, 1));
            pk = pmax(pk, __shfl_xor_sync(0xffffffffu, pk, 2));
            if ((lane & 3) == 0) atomicMax(&g_best[gi], pk);
        }
    }

    // col argmax (symmetry; reduce over lane>>2 : the 8 lanes sharing a column)
#pragma unroll
    for (int j = 0; j < 8; j++) {
#pragma unroll
        for (int q = 0; q < 2; q++) {
            int gj = col0 + wn * 64 + j * 8 + (lane & 3) * 2 + q;
            float bv = -2.f;
            int br = 0;
#pragma unroll
            for (int i = 0; i < 2; i++) {
#pragma unroll
                for (int h = 0; h < 2; h++) {
                    int gi = row0 + wm * 32 + i * 16 + h * 8 + (lane >> 2);
                    float v = acc[i][j][h * 2 + q];
                    if (gi != gj && v > bv) { bv = v; br = gi; }
                }
            }
            unsigned long long pk =
                ((unsigned long long)f2s(bv) << 32) |
                (unsigned long long)(0xFFFFFFFFu - (unsigned)br);
            pk = pmax(pk, __shfl_xor_sync(0xffffffffu, pk, 4));
            pk = pmax(pk, __shfl_xor_sync(0xffffffffu, pk, 8));
            pk = pmax(pk, __shfl_xor_sync(0xffffffffu, pk, 16));
            if ((lane >> 2) == 0) atomicMax(&g_best[gj], pk);
        }
    }
}

// ---------------------------------------------------------------------------
// Kernel 3: per-row NN distance (fp32 vectors), log
// ---------------------------------------------------------------------------
__global__ void dist_kernel() {
    int r = blockIdx.x;
    int t = threadIdx.x;
    unsigned long long pk = g_best[r];
    int j = (int)(0xFFFFFFFFu - (unsigned)(pk & 0xFFFFFFFFu));
    const float* xr = g_x + (size_t)r * D;
    const float* xj = g_x + (size_t)j * D;
    float ss = 0.f;
    for (int k = t; k < D; k += 128) {
        float d = xr[k] - xj[k] + 1e-8f;
        ss += d * d;
    }
    __shared__ float red[128];
    red[t] = ss;
    __syncthreads();
#pragma unroll
    for (int s = 64; s > 0; s >>= 1) {
        if (t < s) red[t] += red[t + s];
        __syncthreads();
    }
    if (t == 0) g_logd[r] = logf(sqrtf(red[0]) + 1e-8f);
}

// ---------------------------------------------------------------------------
// Kernel 4: final mean
// ---------------------------------------------------------------------------
__global__ void reduce_kernel(float* __restrict__ out) {
    __shared__ float red[512];
    int t = threadIdx.x;
    float s = 0.f;
    for (int i = t; i < N; i += 512) s += g_logd[i];
    red[t] = s;
    __syncthreads();
#pragma unroll
    for (int k = 256; k > 0; k >>= 1) {
        if (t < k) red[t] += red[t + k];
        __syncthreads();
    }
    if (t == 0) out[0] = -red[0] / (float)N;
}

extern "C" void kernel_launch(void* const* d_in, const int* in_sizes, int n_in,
                              void* d_out, int out_size) {
    const float* a = (const float*)d_in[0];
    const float* b = (const float*)d_in[1];
    float* out = (float*)d_out;

    cudaFuncSetAttribute(gemm_argmax_hmma,
                         cudaFuncAttributeMaxDynamicSharedMemorySize, SMEM_TOTAL);

    normalize_kernel<<<N, 256>>>(a, b);

    dim3 grid(NB, NB);
    gemm_argmax_hmma<<<grid, 256, SMEM_TOTAL>>>();

    dist_kernel<<<N, 128>>>();
    reduce_kernel<<<1, 512>>>(out);
}